// round 1
// baseline (speedup 1.0000x reference)
#include <cuda_runtime.h>
#include <math.h>

#define HWPX 16384      // 128*128
#define NIMG 2048       // 128 bg * 16 c
#define NBG  128
#define CG   16
#define EPSF 1e-5f

// ---------------- scratch (static __device__, no allocations) ----------------
__device__ float  d_hw[NIMG * 256];    // [img][l]: l<128 row means, l>=128 col means
__device__ float  d_s1[NIMG * 256];    // silu(hw1): [img][l]
__device__ float  d_s2[NIMG * 256];    // silu(hw2)
__device__ float4 d_stats[NIMG];       // (S1, Q1, S2, Q2)
__device__ float  d_k1[NIMG];
__device__ float  d_k2[NIMG];
__device__ float  d_Cc[NBG];

__device__ __forceinline__ float siluf(float v) { return v / (1.0f + expf(-v)); }

// ---------------- K1: per-(bg,c) row means + col means ----------------
// grid 2048, block 128. tx = lane (float4 column group), ty = warp (row phase)
__global__ void k1_rowcol(const float* __restrict__ x) {
    int img = blockIdx.x;
    const float* g = x + (size_t)img * HWPX;
    int tid = threadIdx.x;
    int tx = tid & 31, ty = tid >> 5;

    float4 cs = make_float4(0.f, 0.f, 0.f, 0.f);
    __shared__ float rsum[128];
    __shared__ float csum[4][128];

    for (int i = ty; i < 128; i += 4) {
        float4 v = ((const float4*)(g + i * 128))[tx];
        cs.x += v.x; cs.y += v.y; cs.z += v.z; cs.w += v.w;
        float r = (v.x + v.y) + (v.z + v.w);
        #pragma unroll
        for (int off = 16; off; off >>= 1) r += __shfl_down_sync(0xffffffffu, r, off);
        if (tx == 0) rsum[i] = r;
    }
    csum[ty][4 * tx + 0] = cs.x;
    csum[ty][4 * tx + 1] = cs.y;
    csum[ty][4 * tx + 2] = cs.z;
    csum[ty][4 * tx + 3] = cs.w;
    __syncthreads();

    float* o = d_hw + (size_t)img * 256;
    o[tid]       = rsum[tid] * (1.0f / 128.0f);
    o[128 + tid] = (csum[0][tid] + csum[1][tid] + csum[2][tid] + csum[3][tid]) * (1.0f / 128.0f);
}

// ---------------- kA: 1x1 matmul branch + 3-tap conv branch + silu ----------------
// grid 128 (bg), block 256 (l). hw padded so the conv crosses the h/w concat
// boundary exactly like the reference (concat then conv over length 256).
__global__ void kA_mix(const float* __restrict__ w1, const float* __restrict__ b1,
                       const float* __restrict__ w3, const float* __restrict__ b3) {
    int bg  = blockIdx.x;
    int tid = threadIdx.x;   // l = tid

    __shared__ float hw[16][258];   // hw[c][l+1], zero-padded at both ends
    __shared__ float w1s[256];      // w1[o][i]
    __shared__ float w3s[768];      // w3[o][i][kh] (center column kw=1)
    __shared__ float b1s[16], b3s[16];

    #pragma unroll
    for (int c = 0; c < 16; c++) hw[c][tid + 1] = d_hw[(bg * 16 + c) * 256 + tid];
    if (tid < 16) {
        hw[tid][0] = 0.f; hw[tid][257] = 0.f;
        b1s[tid] = b1[tid]; b3s[tid] = b3[tid];
    }
    w1s[tid] = w1[tid];
    for (int idx = tid; idx < 768; idx += 256) w3s[idx] = w3[idx * 3 + 1]; // kw=1
    __syncthreads();

    int l = tid;
    #pragma unroll
    for (int o = 0; o < 16; o++) {
        float a1 = b1s[o], a2 = b3s[o];
        #pragma unroll
        for (int i = 0; i < 16; i++) {
            float h0 = hw[i][l];       // in[l-1]
            float h1 = hw[i][l + 1];   // in[l]
            float h2 = hw[i][l + 2];   // in[l+1]
            a1 += w1s[o * 16 + i] * h1;
            int wb = (o * 16 + i) * 3;
            a2 += w3s[wb + 0] * h0 + w3s[wb + 1] * h1 + w3s[wb + 2] * h2;
        }
        d_s1[(bg * 16 + o) * 256 + l] = siluf(a1);
        d_s2[(bg * 16 + o) * 256 + l] = siluf(a2);
    }
}

// ---------------- K2: per-(bg,c) sums of y and y^2 for both branches ----------------
// grid 2048, block 256
__global__ void k2_stats(const float* __restrict__ x) {
    int img = blockIdx.x;
    const float* g = x + (size_t)img * HWPX;
    int tid = threadIdx.x;
    int tx = tid & 31, ty = tid >> 5;

    __shared__ float  h1s[128], h2s[128];
    __shared__ float4 w1v[32],  w2v[32];
    if (tid < 128) {
        h1s[tid] = d_s1[img * 256 + tid];
        h2s[tid] = d_s2[img * 256 + tid];
    }
    if (tid < 32) {
        w1v[tid] = ((const float4*)(d_s1 + img * 256 + 128))[tid];
        w2v[tid] = ((const float4*)(d_s2 + img * 256 + 128))[tid];
    }
    __syncthreads();

    float s1 = 0.f, q1 = 0.f, s2 = 0.f, q2 = 0.f;
    for (int i = ty; i < 128; i += 8) {
        float4 v = ((const float4*)(g + i * 128))[tx];
        float h1 = h1s[i], h2 = h2s[i];
        float4 wa = w1v[tx], wb = w2v[tx];
        float p;
        p = v.x * h1 * wa.x; s1 += p; q1 += p * p;
        p = v.y * h1 * wa.y; s1 += p; q1 += p * p;
        p = v.z * h1 * wa.z; s1 += p; q1 += p * p;
        p = v.w * h1 * wa.w; s1 += p; q1 += p * p;
        p = v.x * h2 * wb.x; s2 += p; q2 += p * p;
        p = v.y * h2 * wb.y; s2 += p; q2 += p * p;
        p = v.z * h2 * wb.z; s2 += p; q2 += p * p;
        p = v.w * h2 * wb.w; s2 += p; q2 += p * p;
    }
    #pragma unroll
    for (int off = 16; off; off >>= 1) {
        s1 += __shfl_down_sync(0xffffffffu, s1, off);
        q1 += __shfl_down_sync(0xffffffffu, q1, off);
        s2 += __shfl_down_sync(0xffffffffu, s2, off);
        q2 += __shfl_down_sync(0xffffffffu, q2, off);
    }
    __shared__ float red[8][4];
    if (tx == 0) { red[ty][0] = s1; red[ty][1] = q1; red[ty][2] = s2; red[ty][3] = q2; }
    __syncthreads();
    if (tid == 0) {
        float4 st = make_float4(0.f, 0.f, 0.f, 0.f);
        #pragma unroll
        for (int w = 0; w < 8; w++) {
            st.x += red[w][0]; st.y += red[w][1];
            st.z += red[w][2]; st.w += red[w][3];
        }
        d_stats[img] = st;
    }
}

// ---------------- kB: softmax(gn_b) (exact identity for x1/x2 channel means),
// per-channel norm scalars k1/k2 and per-bg constant C ----------------
// grid 128 (bg), block 32
__global__ void kB_scalars(const float* __restrict__ gn_w, const float* __restrict__ gn_b) {
    int bg = blockIdx.x;
    int c  = threadIdx.x;
    float gb = (c < 16) ? gn_b[c] : -1e30f;
    float m = gb;
    #pragma unroll
    for (int off = 8; off; off >>= 1) m = fmaxf(m, __shfl_xor_sync(0xffffffffu, m, off, 16));
    float e = (c < 16) ? expf(gb - m) : 0.f;
    float se = e;
    #pragma unroll
    for (int off = 8; off; off >>= 1) se += __shfl_xor_sync(0xffffffffu, se, off, 16);

    float part = 0.f;
    if (c < 16) {
        float a = e / se;                    // a1 == a2 == softmax(gn_b)
        float4 st = d_stats[bg * 16 + c];
        float mu1 = st.x * (1.0f / 16384.0f);
        float v1  = st.y * (1.0f / 16384.0f) - mu1 * mu1;
        float r1  = rsqrtf(v1 + EPSF);
        float mu2 = st.z * (1.0f / 16384.0f);
        float v2  = st.w * (1.0f / 16384.0f) - mu2 * mu2;
        float r2  = rsqrtf(v2 + EPSF);
        float gw  = gn_w[c];
        d_k1[bg * 16 + c] = a * gw * r1;
        d_k2[bg * 16 + c] = a * gw * r2;
        part = a * (2.0f * gn_b[c] - gw * (mu1 * r1 + mu2 * r2));
    }
    #pragma unroll
    for (int off = 16; off; off >>= 1) part += __shfl_down_sync(0xffffffffu, part, off);
    if (c == 0) d_Cc[bg] = part;
}

// ---------------- K3: wts reconstruction + final gate + output ----------------
// grid (4 row-chunks, 128 bg), block 256. Each thread owns a float4 of columns;
// gx for all 16 channels is stashed in registers so x is read exactly once here.
__global__ void k3_out(const float* __restrict__ x, float* __restrict__ out) {
    int bg    = blockIdx.y;
    int row0  = blockIdx.x * 32;
    int tid   = threadIdx.x;

    __shared__ float4 sw1v[16][32], sw2v[16][32];   // j-side silu values (float4 banks)
    __shared__ float  th1[16][32],  th2[16][32];    // k * i-side silu values for this chunk
    __shared__ float  Cs;

    for (int idx = tid; idx < 16 * 32; idx += 256) {
        int c = idx >> 5, t = idx & 31;
        sw1v[c][t] = ((const float4*)(d_s1 + (bg * 16 + c) * 256 + 128))[t];
        sw2v[c][t] = ((const float4*)(d_s2 + (bg * 16 + c) * 256 + 128))[t];
        th1[c][t] = d_k1[bg * 16 + c] * d_s1[(bg * 16 + c) * 256 + row0 + t];
        th2[c][t] = d_k2[bg * 16 + c] * d_s2[(bg * 16 + c) * 256 + row0 + t];
    }
    if (tid == 0) Cs = d_Cc[bg];
    __syncthreads();

    int tx = tid & 31, ty = tid >> 5;
    const float* gbase = x   + (size_t)bg * 16 * HWPX;
    float*       obase = out + (size_t)bg * 16 * HWPX;

    for (int rr = 0; rr < 4; rr++) {
        int r = rr * 8 + ty;        // 0..31 within chunk
        int i = row0 + r;
        float4 v[16];
        float4 acc = make_float4(Cs, Cs, Cs, Cs);
        #pragma unroll
        for (int c = 0; c < 16; c++) {
            v[c] = *(const float4*)(gbase + c * HWPX + i * 128 + tx * 4);
            float a1 = th1[c][r], a2 = th2[c][r];
            float4 wa = sw1v[c][tx], wb = sw2v[c][tx];
            acc.x += v[c].x * (a1 * wa.x + a2 * wb.x);
            acc.y += v[c].y * (a1 * wa.y + a2 * wb.y);
            acc.z += v[c].z * (a1 * wa.z + a2 * wb.z);
            acc.w += v[c].w * (a1 * wa.w + a2 * wb.w);
        }
        float4 sw;
        sw.x = siluf(acc.x);
        sw.y = siluf(acc.y);
        sw.z = siluf(acc.z);
        sw.w = siluf(acc.w);
        #pragma unroll
        for (int c = 0; c < 16; c++) {
            float4 o;
            o.x = v[c].x * sw.x;
            o.y = v[c].y * sw.y;
            o.z = v[c].z * sw.z;
            o.w = v[c].w * sw.w;
            *(float4*)(obase + c * HWPX + i * 128 + tx * 4) = o;
        }
    }
}

// ---------------- launch ----------------
extern "C" void kernel_launch(void* const* d_in, const int* in_sizes, int n_in,
                              void* d_out, int out_size) {
    const float* x    = (const float*)d_in[0];
    const float* w1   = (const float*)d_in[1];
    const float* b1   = (const float*)d_in[2];
    const float* w3   = (const float*)d_in[3];
    const float* b3   = (const float*)d_in[4];
    const float* gn_w = (const float*)d_in[5];
    const float* gn_b = (const float*)d_in[6];
    float* out = (float*)d_out;

    k1_rowcol<<<2048, 128>>>(x);
    kA_mix<<<128, 256>>>(w1, b1, w3, b3);
    k2_stats<<<2048, 256>>>(x);
    kB_scalars<<<128, 32>>>(gn_w, gn_b);
    k3_out<<<dim3(4, 128), 256>>>(x, out);
}

// round 2
// speedup vs baseline: 1.4170x; 1.4170x over previous
#include <cuda_runtime.h>
#include <math.h>

#define HWPX 16384        // 128*128
#define EPSF 1e-5f

__device__ __forceinline__ float siluf(float v) { return v / (1.0f + __expf(-v)); }

// One block per bg-group (128 blocks, 512 threads). All phases fused:
//   P1 : per-image row/col means            (cold DRAM read of x, ascending rows)
//   kA : 1x1 matmul + 3-tap conv + silu     (smem only)
//   P2 : per-image sums of y, y^2           (L2-warm read, descending rows)
//   kB : softmax(gn_b) identity + norm scalars k1/k2 + constant C (smem only)
//   C  : wts reconstruction + silu gate + output (L2-warm read, ascending; x
//        stashed in registers so it is read exactly once here; streaming stores)
__global__ __launch_bounds__(512, 1)
void mega(const float* __restrict__ x,
          const float* __restrict__ w1, const float* __restrict__ b1,
          const float* __restrict__ w3, const float* __restrict__ b3,
          const float* __restrict__ gnw, const float* __restrict__ gnb,
          float* __restrict__ out)
{
    extern __shared__ float sm[];
    float* s1  = sm;               // [16][256]  silu(hw1): [c][i<128]=h-side, [c][128+j]=w-side
    float* s2  = sm + 4096;        // [16][256]
    float* hwb = sm + 8192;        // [16][258]  row/col means with 1-elem halo

    __shared__ float w1s[256], w3s[768], b1s[16], b3s[16];
    __shared__ float statv[64], k1s[16], k2s[16], cpart[16], gbsh[16];
    __shared__ float Csm;

    const int bg   = blockIdx.x;
    const int tid  = threadIdx.x;
    const int lane = tid & 31;
    const int wid  = tid >> 5;                   // 0..15 : one warp per image/channel
    const float* xb = x   + (size_t)bg * 16 * HWPX;
    float*       ob = out + (size_t)bg * 16 * HWPX;

    // ---- stage tiny weights (independent of P1, overlaps the cold read) ----
    if (tid < 256) w1s[tid] = __ldg(w1 + tid);
    for (int i2 = tid; i2 < 768; i2 += 512) w3s[i2] = __ldg(w3 + i2 * 3 + 1); // kw=1 column
    if (tid < 16) { b1s[tid] = __ldg(b1 + tid); b3s[tid] = __ldg(b3 + tid); gbsh[tid] = __ldg(gnb + tid); }

    // ================= P1: row means + col means (ascending rows) =================
    {
        const int c = wid;
        const float* g = xb + c * HWPX;
        float* hwc = hwb + c * 258;
        float4 cs = make_float4(0.f, 0.f, 0.f, 0.f);
        #pragma unroll 1
        for (int i0 = 0; i0 < 128; i0 += 8) {
            float4 v[8]; float r[8];
            #pragma unroll
            for (int k = 0; k < 8; k++) v[k] = __ldg((const float4*)(g + (i0 + k) * 128) + lane);
            #pragma unroll
            for (int k = 0; k < 8; k++) {
                cs.x += v[k].x; cs.y += v[k].y; cs.z += v[k].z; cs.w += v[k].w;
                r[k] = (v[k].x + v[k].y) + (v[k].z + v[k].w);
            }
            #pragma unroll
            for (int off = 16; off; off >>= 1) {
                #pragma unroll
                for (int k = 0; k < 8; k++) r[k] += __shfl_down_sync(0xffffffffu, r[k], off);
            }
            if (lane == 0) {
                #pragma unroll
                for (int k = 0; k < 8; k++) hwc[1 + i0 + k] = r[k] * (1.f / 128.f);
            }
        }
        // col means: this warp owns all rows, so cs is the complete column sum
        hwc[129 + 4 * lane + 0] = cs.x * (1.f / 128.f);
        hwc[129 + 4 * lane + 1] = cs.y * (1.f / 128.f);
        hwc[129 + 4 * lane + 2] = cs.z * (1.f / 128.f);
        hwc[129 + 4 * lane + 3] = cs.w * (1.f / 128.f);
        if (lane == 0) { hwc[0] = 0.f; hwc[257] = 0.f; }   // conv halo (zero padding)
    }
    __syncthreads();

    // ================= kA: channel mix over concat length 256 =================
    for (int idx = tid; idx < 4096; idx += 512) {
        const int o = idx >> 8, l = idx & 255;
        float a1 = b1s[o], a2 = b3s[o];
        #pragma unroll
        for (int i = 0; i < 16; i++) {
            const float* h = hwb + i * 258 + l;
            const float h0 = h[0], h1 = h[1], h2 = h[2];
            a1 = fmaf(w1s[o * 16 + i], h1, a1);
            const int wb = (o * 16 + i) * 3;
            a2 = fmaf(w3s[wb], h0, fmaf(w3s[wb + 1], h1, fmaf(w3s[wb + 2], h2, a2)));
        }
        s1[o * 256 + l] = siluf(a1);
        s2[o * 256 + l] = siluf(a2);
    }
    __syncthreads();

    // ================= P2: per-image sums of y, y^2 (descending rows) =================
    {
        const int c = wid;
        const float* g = xb + c * HWPX;
        const float4 wa = *(const float4*)(s1 + c * 256 + 128 + 4 * lane);
        const float4 wb = *(const float4*)(s2 + c * 256 + 128 + 4 * lane);
        float sa = 0.f, qa = 0.f, sb = 0.f, qb = 0.f;
        #pragma unroll 1
        for (int i0 = 120; i0 >= 0; i0 -= 8) {
            float4 v[8];
            #pragma unroll
            for (int k = 0; k < 8; k++) v[k] = __ldg((const float4*)(g + (i0 + k) * 128) + lane);
            #pragma unroll
            for (int k = 0; k < 8; k++) {
                const float h1 = s1[c * 256 + i0 + k];   // smem broadcast
                const float h2 = s2[c * 256 + i0 + k];
                float p;
                p = v[k].x * h1 * wa.x; sa += p; qa = fmaf(p, p, qa);
                p = v[k].y * h1 * wa.y; sa += p; qa = fmaf(p, p, qa);
                p = v[k].z * h1 * wa.z; sa += p; qa = fmaf(p, p, qa);
                p = v[k].w * h1 * wa.w; sa += p; qa = fmaf(p, p, qa);
                p = v[k].x * h2 * wb.x; sb += p; qb = fmaf(p, p, qb);
                p = v[k].y * h2 * wb.y; sb += p; qb = fmaf(p, p, qb);
                p = v[k].z * h2 * wb.z; sb += p; qb = fmaf(p, p, qb);
                p = v[k].w * h2 * wb.w; sb += p; qb = fmaf(p, p, qb);
            }
        }
        #pragma unroll
        for (int off = 16; off; off >>= 1) {
            sa += __shfl_down_sync(0xffffffffu, sa, off);
            qa += __shfl_down_sync(0xffffffffu, qa, off);
            sb += __shfl_down_sync(0xffffffffu, sb, off);
            qb += __shfl_down_sync(0xffffffffu, qb, off);
        }
        if (lane == 0) { statv[c * 4] = sa; statv[c * 4 + 1] = qa; statv[c * 4 + 2] = sb; statv[c * 4 + 3] = qb; }
    }
    __syncthreads();

    // ================= kB: scalars =================
    if (tid < 16) {
        float m = -1e30f;
        #pragma unroll
        for (int i = 0; i < 16; i++) m = fmaxf(m, gbsh[i]);
        float se = 0.f;
        #pragma unroll
        for (int i = 0; i < 16; i++) se += __expf(gbsh[i] - m);
        const float a = __expf(gbsh[tid] - m) / se;        // a1 == a2 == softmax(gn_b)
        const float S1 = statv[tid * 4], Q1 = statv[tid * 4 + 1];
        const float S2 = statv[tid * 4 + 2], Q2 = statv[tid * 4 + 3];
        const float mu1 = S1 * (1.f / 16384.f);
        const float r1  = rsqrtf(Q1 * (1.f / 16384.f) - mu1 * mu1 + EPSF);
        const float mu2 = S2 * (1.f / 16384.f);
        const float r2  = rsqrtf(Q2 * (1.f / 16384.f) - mu2 * mu2 + EPSF);
        const float gw = __ldg(gnw + tid);
        k1s[tid] = a * gw * r1;
        k2s[tid] = a * gw * r2;
        cpart[tid] = a * (2.f * gbsh[tid] - gw * (mu1 * r1 + mu2 * r2));
    }
    __syncthreads();
    if (tid == 0) {
        float s = 0.f;
        #pragma unroll
        for (int i = 0; i < 16; i++) s += cpart[i];
        Csm = s;
    }
    // fold k1/k2 into the i-side silu tables (j-side stays unscaled)
    for (int idx = tid; idx < 2048; idx += 512) {
        const int c = idx >> 7, i = idx & 127;
        s1[c * 256 + i] *= k1s[c];
        s2[c * 256 + i] *= k2s[c];
    }
    __syncthreads();

    // ================= C: wts + gate + output (ascending rows, x read once) =================
    {
        const int rloc = tid >> 5;              // 0..15 rows per sub-iteration
        const float Cc = Csm;
        #pragma unroll 1
        for (int s = 0; s < 8; s++) {
            const int i = s * 16 + rloc;
            float4 v[16];
            float4 w4 = make_float4(Cc, Cc, Cc, Cc);
            #pragma unroll
            for (int c = 0; c < 16; c++) {
                v[c] = __ldcs((const float4*)(xb + c * HWPX + i * 128) + lane);
                const float a1 = s1[c * 256 + i];
                const float a2 = s2[c * 256 + i];
                const float4 j1 = *(const float4*)(s1 + c * 256 + 128 + 4 * lane);
                const float4 j2 = *(const float4*)(s2 + c * 256 + 128 + 4 * lane);
                w4.x += v[c].x * fmaf(a1, j1.x, a2 * j2.x);
                w4.y += v[c].y * fmaf(a1, j1.y, a2 * j2.y);
                w4.z += v[c].z * fmaf(a1, j1.z, a2 * j2.z);
                w4.w += v[c].w * fmaf(a1, j1.w, a2 * j2.w);
            }
            float4 sw;
            sw.x = siluf(w4.x); sw.y = siluf(w4.y); sw.z = siluf(w4.z); sw.w = siluf(w4.w);
            #pragma unroll
            for (int c = 0; c < 16; c++) {
                float4 o4;
                o4.x = v[c].x * sw.x; o4.y = v[c].y * sw.y;
                o4.z = v[c].z * sw.z; o4.w = v[c].w * sw.w;
                __stcs((float4*)(ob + c * HWPX + i * 128) + lane, o4);
            }
        }
    }
}

// ---------------- launch ----------------
extern "C" void kernel_launch(void* const* d_in, const int* in_sizes, int n_in,
                              void* d_out, int out_size) {
    const float* x    = (const float*)d_in[0];
    const float* w1   = (const float*)d_in[1];
    const float* b1   = (const float*)d_in[2];
    const float* w3   = (const float*)d_in[3];
    const float* b3   = (const float*)d_in[4];
    const float* gn_w = (const float*)d_in[5];
    const float* gn_b = (const float*)d_in[6];
    float* out = (float*)d_out;

    const int smem_bytes = (4096 + 4096 + 16 * 258) * (int)sizeof(float);  // 49280 B
    static bool attr_done = false;
    if (!attr_done) {
        cudaFuncSetAttribute(mega, cudaFuncAttributeMaxDynamicSharedMemorySize, smem_bytes);
        attr_done = true;
    }
    mega<<<128, 512, smem_bytes>>>(x, w1, b1, w3, b3, gn_w, gn_b, out);
}